// round 1
// baseline (speedup 1.0000x reference)
#include <cuda_runtime.h>

// CTC forward scan: T=4096 steps, B=64 batches, P=512 positions (+pos 0), F=5 feats.
// One CTA per batch. 256 threads; thread i owns fwd positions 2i+1, 2i+2 in registers.
// Per step: neighbor fwd via __shfl_up; warp boundary via double-buffered smem slot;
// fwd[0] maintained redundantly in every thread (running sum of the stay feature).
// x staged in 128-step smem chunks, next chunk prefetched into registers.

#define T_STEPS 4096
#define BATCH 64
#define NFEAT 5
#define P_POS 512
#define NEG_LARGE (-1e30f)
#define CHUNK 128
#define PITCH 132            // CHUNK + 4: feature rows land in distinct smem banks
#define NCHUNK (T_STEPS / CHUNK)
#define NTHREADS 256
#define NWARPS (NTHREADS / 32)
#define CHUNK_ELEMS (CHUNK * NFEAT)   // 640
#define LDPT 3                        // ceil(640 / 256)

__device__ __forceinline__ float lae(float a, float b) {
    // logaddexp, stable: max + log1p(exp(min-max)). Handles -1e30 sentinels:
    // d is always <= 0; exp underflows cleanly; (-1e30)-(-1e30)=0 -> m+ln2 = -1e30 in fp32.
    float m = fmaxf(a, b);
    float d = fminf(a, b) - m;
    return m + __logf(1.0f + __expf(d));
}

__global__ void __launch_bounds__(NTHREADS, 1)
ctc_fwd_kernel(const float* __restrict__ x,
               const int*   __restrict__ seqs,
               const int*   __restrict__ seqlens,
               float*       __restrict__ out)
{
    const int b    = blockIdx.x;
    const int tid  = threadIdx.x;
    const int lane = tid & 31;
    const int w    = tid >> 5;

    __shared__ float xsm[2 * NFEAT * PITCH];   // double-buffered x chunk, [buf][feat][t]
    __shared__ float bnd[2][NWARPS];           // double-buffered warp-boundary fwd values
    __shared__ float ffin[P_POS + 1];          // final fwd vector for epilogue gather

    // Per-thread emit feature indices (constant over t): positions 2*tid+1, 2*tid+2
    // use seqs[b, 2*tid] and seqs[b, 2*tid+1].
    const int si0 = seqs[b * P_POS + 2 * tid];
    const int si1 = seqs[b * P_POS + 2 * tid + 1];
    const int ro0 = si0 * PITCH;
    const int ro1 = si1 * PITCH;

    float f0v   = NEG_LARGE;   // fwd[2*tid+1]
    float f1v   = NEG_LARGE;   // fwd[2*tid+2]
    float fzero = 0.0f;        // fwd[0], maintained identically by all threads

    if (tid < NWARPS) { bnd[0][tid] = NEG_LARGE; bnd[1][tid] = NEG_LARGE; }

    const float* xb = x + b * NFEAT;   // x[t*B*F + b*F + f]

    // ---- prologue: load chunk 0 into smem buffer 0 ----
    {
        #pragma unroll
        for (int k = 0; k < LDPT; ++k) {
            int idx = tid + k * NTHREADS;
            if (idx < CHUNK_ELEMS) {
                int tl = idx / NFEAT;
                int f  = idx - tl * NFEAT;
                xsm[f * PITCH + tl] = xb[tl * (BATCH * NFEAT) + f];
            }
        }
    }
    __syncthreads();

    int t = 0;
    for (int c = 0; c < NCHUNK; ++c) {
        // ---- prefetch next chunk into registers (LDG latency hidden by compute) ----
        float nv[LDPT];
        const bool more = (c + 1 < NCHUNK);
        if (more) {
            const int t0 = (c + 1) * CHUNK;
            #pragma unroll
            for (int k = 0; k < LDPT; ++k) {
                int idx = tid + k * NTHREADS;
                if (idx < CHUNK_ELEMS) {
                    int tl = idx / NFEAT;
                    int f  = idx - tl * NFEAT;
                    nv[k] = xb[(t0 + tl) * (BATCH * NFEAT) + f];
                }
            }
        }

        const float* xs = xsm + (c & 1) * (NFEAT * PITCH);

        #pragma unroll 4
        for (int tc = 0; tc < CHUNK; ++tc, ++t) {
            // emit + stay features for this step (broadcast / conflict-free LDS)
            float e0   = xs[ro0 + tc];
            float e1   = xs[ro1 + tc];
            float xstv = xs[4 * PITCH + tc];

            // left neighbor fwd value (old): intra-warp via shfl, cross-warp via smem
            float up = __shfl_up_sync(0xffffffffu, f1v, 1);
            float L  = up;
            if (lane == 0) L = (w == 0) ? fzero : bnd[(t & 1) ^ 1][w - 1];

            // two independent logaddexp updates (all inputs are step-(t-1) values)
            float n0 = lae(e0 + L,   xstv + f0v);
            float n1 = lae(e1 + f0v, xstv + f1v);

            fzero += xstv;          // fwd[0] update (uses old fzero above)
            f0v = n0;
            f1v = n1;

            if (lane == 31) bnd[t & 1][w] = n1;   // publish boundary for next step
            __syncthreads();
        }

        // ---- commit prefetched chunk to the other smem buffer ----
        if (more) {
            float* xd = xsm + ((c + 1) & 1) * (NFEAT * PITCH);
            #pragma unroll
            for (int k = 0; k < LDPT; ++k) {
                int idx = tid + k * NTHREADS;
                if (idx < CHUNK_ELEMS) {
                    int tl = idx / NFEAT;
                    int f  = idx - tl * NFEAT;
                    xd[f * PITCH + tl] = nv[k];
                }
            }
            __syncthreads();
        }
    }

    // ---- epilogue: gather fwd[seqlens[b]] ----
    ffin[2 * tid + 1] = f0v;
    ffin[2 * tid + 2] = f1v;
    if (tid == 0) ffin[0] = fzero;
    __syncthreads();
    if (tid == 0) {
        int sl = seqlens[b];
        out[b] = -ffin[sl] * (1.0f / (float)T_STEPS);
    }
}

extern "C" void kernel_launch(void* const* d_in, const int* in_sizes, int n_in,
                              void* d_out, int out_size)
{
    const float* x       = (const float*)d_in[0];
    const int*   seqs    = (const int*)  d_in[1];
    const int*   seqlens = (const int*)  d_in[2];
    float*       out     = (float*)      d_out;

    ctc_fwd_kernel<<<BATCH, NTHREADS>>>(x, seqs, seqlens, out);
}